// round 14
// baseline (speedup 1.0000x reference)
#include <cuda_runtime.h>
#include <math.h>

// ============================================================================
// PhasorTransformer, linear-algebra collapsed form.
//
// zf[0] = e^{i w31[0]} * sum_t e^{i w00[t]} * r[t] * e^{i x[t]},
//   r = F(m1 .* F(m2 .* F(m3)))  (F = unnormalized DFT, F^T = F; ortho
//   scalings drop out of angle; asin(sin(.)) = exact triangular wrap).
//
// R14: single change vs R13 — dot TPB 512 -> 256 (7 blocks/SM by regs,
// 87% theoretical occupancy vs 75%). Depth-2 x prefetch kept (R13-proven).
// Precompute = R6 float Stockham (best measured), untouched.
// ============================================================================

#define NFFT 2048

__device__ float g_rre[NFFT];
__device__ float g_rim[NFFT];

// ---------------------------------------------------------------- precompute
#define PRE_T 1024

__global__ void __launch_bounds__(PRE_T)
precompute_kernel(const float* __restrict__ w) {
    __shared__ float br[2][NFFT];
    __shared__ float bi[2][NFFT];
    __shared__ float twr[NFFT / 2];
    __shared__ float twi[NFFT / 2];
    const int tid = threadIdx.x;

    {   // twiddles exp(-2*pi*i*k/2048), k < 1024
        float a = -6.2831853071795864769f * (float)tid / (float)NFFT;
        float s, c;
        sincosf(a, &s, &c);
        twr[tid] = c;
        twi[tid] = s;
    }
    // buffer 0 = m3 = exp(i(w21 + w30))
#pragma unroll
    for (int k = 0; k < 2; k++) {
        int e = tid + PRE_T * k;
        float a = w[10240 + e] + w[12288 + e];
        float s, c;
        sincosf(a, &s, &c);
        br[0][e] = c;
        bi[0][e] = s;
    }
    __syncthreads();

    int cur = 0;
    for (int f = 0; f < 3; f++) {
        // 11 Stockham radix-2 stages, natural-order output, 1 butterfly/thread
        for (int t = 0; t < 11; t++) {
            const int s = 1 << t;
            const int nxt = cur ^ 1;
            const int n = tid;
            const int p = n >> t;
            const int q = n & (s - 1);
            const int j0 = q + (p << (t + 1));
            const int j1 = j0 + s;
            float ar = br[cur][n],             ai = bi[cur][n];
            float crr = br[cur][n + NFFT / 2], cii = bi[cur][n + NFFT / 2];
            float sr = ar + crr, si = ai + cii;
            float dr = ar - crr, di = ai - cii;
            float wr = twr[p << t], wi = twi[p << t];
            float er = fmaf(dr, wr, -di * wi);
            float ei = fmaf(dr, wi,  di * wr);
            br[nxt][j0] = sr; bi[nxt][j0] = si;
            br[nxt][j1] = er; bi[nxt][j1] = ei;
            cur = nxt;
            __syncthreads();
        }
        if (f < 2) {
            const int o1 = (f == 0) ? 6144 : 2048;
            const int o2 = (f == 0) ? 8192 : 4096;
#pragma unroll
            for (int k = 0; k < 2; k++) {
                int e = tid + PRE_T * k;
                float a = w[o1 + e] + w[o2 + e];
                float s, c;
                sincosf(a, &s, &c);
                float vr = br[cur][e], vi = bi[cur][e];
                br[cur][e] = fmaf(vr, c, -vi * s);
                bi[cur][e] = fmaf(vr, s,  vi * c);
            }
            __syncthreads();
        }
    }

    const float w310 = w[14336];
#pragma unroll
    for (int k = 0; k < 2; k++) {
        int e = tid + PRE_T * k;
        float a = w[e] + w310;
        float s, c;
        sincosf(a, &s, &c);
        float vr = br[cur][e], vi = bi[cur][e];
        g_rre[e] = fmaf(vr, c, -vi * s);
        g_rim[e] = fmaf(vr, s,  vi * c);
    }
}

// ---------------------------------------------------------------- main kernel
// warp-per-row complex dot product: S = sum_t r''[t] e^{i x[t]}
#define TPB 256
#define WPB (TPB / 32)

__device__ __forceinline__ void acc4(float4 xv, float4 rr, float4 ri,
                                     float& ax, float& ay) {
    float s, c;
    __sincosf(xv.x, &s, &c);
    ax = fmaf(rr.x, c, ax); ax = fmaf(-ri.x, s, ax);
    ay = fmaf(rr.x, s, ay); ay = fmaf( ri.x, c, ay);
    __sincosf(xv.y, &s, &c);
    ax = fmaf(rr.y, c, ax); ax = fmaf(-ri.y, s, ax);
    ay = fmaf(rr.y, s, ay); ay = fmaf( ri.y, c, ay);
    __sincosf(xv.z, &s, &c);
    ax = fmaf(rr.z, c, ax); ax = fmaf(-ri.z, s, ax);
    ay = fmaf(rr.z, s, ay); ay = fmaf( ri.z, c, ay);
    __sincosf(xv.w, &s, &c);
    ax = fmaf(rr.w, c, ax); ax = fmaf(-ri.w, s, ax);
    ay = fmaf(rr.w, s, ay); ay = fmaf( ri.w, c, ay);
}

__global__ void __launch_bounds__(TPB)
dot_kernel(const float* __restrict__ x, float* __restrict__ out, int rows) {
    __shared__ float sR[NFFT], sI[NFFT];
    const int tid = threadIdx.x;
    for (int i = tid; i < NFFT; i += TPB) {
        sR[i] = g_rre[i];
        sI[i] = g_rim[i];
    }
    __syncthreads();

    const int warp = tid >> 5;
    const int lane = tid & 31;
    const float4* sR4 = (const float4*)sR;
    const float4* sI4 = (const float4*)sI;

    for (int row = blockIdx.x * WPB + warp; row < rows; row += gridDim.x * WPB) {
        const float4* xr = (const float4*)(x + (size_t)row * NFFT);
        float ax = 0.f, ay = 0.f;

        // 2-deep rotating prefetch of x; table reads stay in the loop body.
        float4 x0 = __ldg(&xr[lane]);
        float4 x1 = __ldg(&xr[lane + 32]);
#pragma unroll
        for (int j = 0; j < 16; j++) {
            float4 xn = (j < 14) ? __ldg(&xr[lane + 32 * (j + 2)]) : x0;
            int e4 = lane + 32 * j;
            float4 rr = sR4[e4];
            float4 ri = sI4[e4];
            acc4(x0, rr, ri, ax, ay);
            x0 = x1;
            x1 = xn;
        }
#pragma unroll
        for (int off = 16; off > 0; off >>= 1) {
            ax += __shfl_xor_sync(0xffffffffu, ax, off);
            ay += __shfl_xor_sync(0xffffffffu, ay, off);
        }
        if (lane == 0) {
            float th = atan2f(ay, ax);
            const float PI_F = 3.14159265358979323846f;
            const float HPI  = 1.57079632679489661923f;
            if (th >  HPI)      th =  PI_F - th;
            else if (th < -HPI) th = -PI_F - th;
            out[row] = th;
        }
    }
}

// ---------------------------------------------------------------- launch
extern "C" void kernel_launch(void* const* d_in, const int* in_sizes, int n_in,
                              void* d_out, int out_size) {
    const float* x = (const float*)d_in[0];
    const float* w = (const float*)d_in[1];
    float* out = (float*)d_out;
    const int rows = in_sizes[0] / NFFT;
    if (rows <= 0) return;

    precompute_kernel<<<1, PRE_T>>>(w);

    int grid = (rows + WPB - 1) / WPB;     // one row per warp
    if (grid < 1) grid = 1;
    dot_kernel<<<grid, TPB>>>(x, out, rows);
}